// round 11
// baseline (speedup 1.0000x reference)
#include <cuda_runtime.h>
#include <cuda_bf16.h>
#include <stdint.h>

#define N_NODES 4096
#define KNBR 32
#define CDIM 128
#define VDIM 21
#define NUM_TILES (N_NODES / 4)   // 4 nodes per tile, M = 128 rows
#define BWORDS 8192               // packed B fragments: 32 KB
#define DYN_SMEM (BWORDS * 4)
#define TPAD 132                  // sT row stride (float4-aligned)

__device__ float g_A[CDIM];
__device__ float g_const[CDIM];
__device__ float g_T[VDIM * CDIM];

__device__ __forceinline__ float lrelu(float x) { return x > 0.f ? x : 0.2f * x; }

__device__ __forceinline__ uint32_t cvt2(float2 v) {
    __nv_bfloat162 p = __floats2bfloat162_rn(v.x, v.y);
    return *(uint32_t*)&p;
}
__device__ __forceinline__ void mma16816(float* c, uint32_t a0, uint32_t a1,
                                         uint32_t a2, uint32_t a3,
                                         uint32_t b0, uint32_t b1) {
    asm volatile("mma.sync.aligned.m16n8k16.row.col.f32.bf16.bf16.f32 "
                 "{%0,%1,%2,%3}, {%4,%5,%6,%7}, {%8,%9}, {%0,%1,%2,%3};"
                 : "+f"(c[0]), "+f"(c[1]), "+f"(c[2]), "+f"(c[3])
                 : "r"(a0), "r"(a1), "r"(a2), "r"(a3), "r"(b0), "r"(b1));
}

// 22 blocks x 128 threads: block 0 -> g_A/g_const, blocks 1..21 -> g_T rows.
__global__ void setup_kernel(const float* __restrict__ bl1, const float* __restrict__ bo1,
                             const float* __restrict__ Wl2, const float* __restrict__ bl2,
                             const float* __restrict__ Wr2, const float* __restrict__ br2,
                             const float* __restrict__ be2, const float* __restrict__ Ws) {
    int c = threadIdx.x;
    int b = blockIdx.x;
    if (b == 0) {
        __shared__ float nv[CDIM];
        nv[c] = bl1[c] + bo1[c];
        __syncthreads();
        float a = 0.f, x = 0.f;
        #pragma unroll 8
        for (int j = 0; j < CDIM; j++) {
            a = fmaf(nv[j], Wl2[j * CDIM + c], a);
            x = fmaf(nv[j], Wr2[j * CDIM + c], x);
        }
        g_A[c] = a;
        g_const[c] = x + br2[c] + bl2[c] + be2[c];
    } else {
        int v = b - 1;
        float t = 0.f;
        #pragma unroll 8
        for (int h = 0; h < CDIM; h++)
            t = fmaf(Ws[v * CDIM + h], Wl2[(CDIM + h) * CDIM + c], t);
        g_T[v * CDIM + c] = t;
    }
}

__global__ void __launch_bounds__(256, 2)
main_kernel(const float* __restrict__ E, const int* __restrict__ E_idx,
            const int* __restrict__ S, const float* __restrict__ mask,
            const float* __restrict__ chain_M, const float* __restrict__ z,
            const float* __restrict__ We2, const float* __restrict__ a2,
            const float* __restrict__ bl2, const float* __restrict__ bo2,
            const float* __restrict__ W_out, const float* __restrict__ b_out,
            float* __restrict__ out) {
    extern __shared__ uint32_t Bsm[];       // packed We2^T fragments (LDS.64 order)

    __shared__ float sT[VDIM * TPAD];
    __shared__ float sGA[CDIM];
    __shared__ float sGC[CDIM];
    __shared__ float sa2[CDIM];
    __shared__ float sB2[CDIM];             // bl2 + bo2
    __shared__ float sWk[128];
    __shared__ int   sSk[128];
    __shared__ float sLogit[128];
    __shared__ float sMask[4];
    __shared__ float sOut[4 * TPAD];

    const int tid  = threadIdx.x;
    const int w    = tid >> 5;              // 0..7
    const int lane = tid & 31;
    const int gq   = lane >> 2;             // 0..7
    const int tq   = lane & 3;              // 0..3

    // ---- one-time init ----
    // Packed B: dest word i holds bf16x2 of We2[2jw][n], We2[2jw+1][n]
    // with i = ((nt*8+s)*32 + gq*4 + tq)*2 + b1, jw = s*8 + tq + 4*b1, n = nt*8+gq.
    for (int i = tid; i < BWORDS; i += 256) {
        int b1 = i & 1;
        int t2 = i >> 1;
        int tq2 = t2 & 3, gq2 = (t2 >> 2) & 7, s2 = (t2 >> 5) & 7, nt2 = t2 >> 8;
        int n  = nt2 * 8 + gq2;
        int j0 = (s2 * 8 + tq2 + 4 * b1) * 2;
        __nv_bfloat162 p = __floats2bfloat162_rn(We2[j0 * CDIM + n],
                                                 We2[(j0 + 1) * CDIM + n]);
        Bsm[i] = *(uint32_t*)&p;
    }
    for (int i = tid; i < VDIM * CDIM; i += 256)
        sT[(i >> 7) * TPAD + (i & 127)] = g_T[i];
    if (tid < CDIM) {
        sGA[tid] = g_A[tid];
        sGC[tid] = g_const[tid];
        sa2[tid] = a2[tid];
        sB2[tid] = bl2[tid] + bo2[tid];
    }
    __syncthreads();

    const int r0 = 16 * w + gq, r1 = r0 + 8;
    const int nd = w >> 1;
    const uint2* Bp = (const uint2*)Bsm + (gq * 4 + tq);

    for (int tile = blockIdx.x; tile < NUM_TILES; tile += gridDim.x) {
        // metadata (warps 0-3); safe: runs after this group's previous-tile tail
        if (tid < 128) {
            int n = tile * 4 + (tid >> 5);
            int k = tid & 31;
            int e = E_idx[n * KNBR + k];
            float kn = __fmul_rn(__fadd_rn(__fmul_rn(chain_M[n], mask[n]), 1e-4f), fabsf(z[n]));
            float ke = __fmul_rn(__fadd_rn(__fmul_rn(chain_M[e], mask[e]), 1e-4f), fabsf(z[e]));
            float attend = (kn > ke || (kn == ke && n > e)) ? 1.f : 0.f;
            sWk[tid] = attend * mask[n];
            sSk[tid] = S[e];
            if (k == 0) sMask[tid >> 5] = mask[n];
        }

        // ---- GEMM: A fragments straight from gmem (fp32->bf16 in regs) ----
        const float2* pr0 = (const float2*)E + ((size_t)tile * 128 + r0) * 64 + tq;
        const float2* pr1 = pr0 + 8 * 64;

        float acc[16][4];
        #pragma unroll
        for (int nt = 0; nt < 16; nt++)
            #pragma unroll
            for (int i = 0; i < 4; i++) acc[nt][i] = 0.f;

        float2 st[8];
        #pragma unroll
        for (int s2 = 0; s2 < 2; s2++) {          // prologue: s = 0,1
            st[s2 * 4 + 0] = pr0[8 * s2];
            st[s2 * 4 + 1] = pr0[8 * s2 + 4];
            st[s2 * 4 + 2] = pr1[8 * s2];
            st[s2 * 4 + 3] = pr1[8 * s2 + 4];
        }
        #pragma unroll
        for (int q = 0; q < 4; q++) {
            uint32_t wf[8];
            #pragma unroll
            for (int u = 0; u < 8; u++) wf[u] = cvt2(st[u]);
            if (q < 3) {
                #pragma unroll
                for (int s2 = 0; s2 < 2; s2++) {  // prefetch s = 2q+2, 2q+3
                    int s = (q + 1) * 2 + s2;
                    st[s2 * 4 + 0] = pr0[8 * s];
                    st[s2 * 4 + 1] = pr0[8 * s + 4];
                    st[s2 * 4 + 2] = pr1[8 * s];
                    st[s2 * 4 + 3] = pr1[8 * s + 4];
                }
            }
            #pragma unroll
            for (int s2 = 0; s2 < 2; s2++) {
                const int s = q * 2 + s2;
                // fragment order: a0=(r0,jo) a1=(r1,jo) a2=(r0,jo+4) a3=(r1,jo+4)
                const uint32_t a0 = wf[s2 * 4 + 0], a2r = wf[s2 * 4 + 1];
                const uint32_t a1 = wf[s2 * 4 + 2], a3  = wf[s2 * 4 + 3];
                #pragma unroll
                for (int nt = 0; nt < 16; nt++) {
                    uint2 b = Bp[(nt * 8 + s) * 32];
                    mma16816(acc[nt], a0, a1, a2r, a3, b.x, b.y);
                }
            }
        }
        __syncthreads();   // A: metadata visible; prev-tile tail finished

        // ---- epilogue: attention logits ----
        {
            const float mn  = sMask[nd];
            const float wk0 = sWk[r0], wk1 = sWk[r1];
            const float* T0 = &sT[sSk[r0] * TPAD];
            const float* T1 = &sT[sSk[r1] * TPAD];
            float p0 = 0.f, p1 = 0.f;
            #pragma unroll
            for (int nt = 0; nt < 16; nt++) {
                #pragma unroll
                for (int i = 0; i < 2; i++) {
                    const int c = nt * 8 + tq * 2 + i;
                    const float ad = fmaf(sGA[c], mn, sGC[c]);
                    const float av = sa2[c];
                    p0 = fmaf(lrelu(acc[nt][i]     + ad + T0[c] * wk0), av, p0);
                    p1 = fmaf(lrelu(acc[nt][2 + i] + ad + T1[c] * wk1), av, p1);
                }
            }
            p0 += __shfl_xor_sync(0xffffffffu, p0, 1);
            p0 += __shfl_xor_sync(0xffffffffu, p0, 2);
            p1 += __shfl_xor_sync(0xffffffffu, p1, 1);
            p1 += __shfl_xor_sync(0xffffffffu, p1, 2);
            if (tq == 0) { sLogit[r0] = p0; sLogit[r1] = p1; }
        }
        __syncthreads();   // B: sLogit ready; warps 4-7 run ahead to next tile

        // ---- tail (warps 0-3, node = w): softmax + output + V-proj ----
        if (w < 4) {
            float logit = sLogit[w * 32 + lane];
            float mx = logit;
            #pragma unroll
            for (int off = 16; off; off >>= 1)
                mx = fmaxf(mx, __shfl_xor_sync(0xffffffffu, mx, off));
            float e = expf(logit - mx);
            float ssum = e;
            #pragma unroll
            for (int off = 16; off; off >>= 1)
                ssum += __shfl_xor_sync(0xffffffffu, ssum, off);
            float aw = (e / ssum) * sWk[w * 32 + lane];
            int   sk = sSk[w * 32 + lane];

            const float mn = sMask[w];
            const int c0 = lane * 4;
            float o0 = fmaf(sGA[c0],     mn, sB2[c0]);
            float o1 = fmaf(sGA[c0 + 1], mn, sB2[c0 + 1]);
            float o2 = fmaf(sGA[c0 + 2], mn, sB2[c0 + 2]);
            float o3 = fmaf(sGA[c0 + 3], mn, sB2[c0 + 3]);
            #pragma unroll
            for (int k = 0; k < KNBR; k++) {
                float awk = __shfl_sync(0xffffffffu, aw, k);
                int   skk = __shfl_sync(0xffffffffu, sk, k);
                const float4 t = *(const float4*)&sT[skk * TPAD + c0];
                o0 = fmaf(awk, t.x, o0);
                o1 = fmaf(awk, t.y, o1);
                o2 = fmaf(awk, t.z, o2);
                o3 = fmaf(awk, t.w, o3);
            }
            *(float4*)&sOut[w * TPAD + c0] = make_float4(o0, o1, o2, o3);
            __syncwarp();

            float L = -1e30f;
            if (lane < VDIM) {
                L = b_out[lane];
                const float* sO = &sOut[w * TPAD];
                #pragma unroll 8
                for (int c = 0; c < CDIM; c++)
                    L = fmaf(sO[c], W_out[c * VDIM + lane], L);
            }
            float mx2 = L;
            #pragma unroll
            for (int off = 16; off; off >>= 1)
                mx2 = fmaxf(mx2, __shfl_xor_sync(0xffffffffu, mx2, off));
            float e2 = (lane < VDIM) ? expf(L - mx2) : 0.f;
            float s2 = e2;
            #pragma unroll
            for (int off = 16; off; off >>= 1)
                s2 += __shfl_xor_sync(0xffffffffu, s2, off);
            if (lane < VDIM)
                out[(tile * 4 + w) * VDIM + lane] = L - mx2 - logf(s2);
        }
        // no trailing barrier: next-tile barrier A provides the ordering
    }
}

extern "C" void kernel_launch(void* const* d_in, const int* in_sizes, int n_in,
                              void* d_out, int out_size) {
    const float* E       = (const float*)d_in[0];
    const int*   E_idx   = (const int*)  d_in[1];
    const int*   S       = (const int*)  d_in[2];
    const float* mask    = (const float*)d_in[3];
    const float* chain_M = (const float*)d_in[4];
    const float* z       = (const float*)d_in[5];
    const float* bl1     = (const float*)d_in[7];
    const float* bo1     = (const float*)d_in[13];
    const float* Wl2     = (const float*)d_in[14];
    const float* bl2     = (const float*)d_in[15];
    const float* Wr2     = (const float*)d_in[16];
    const float* br2     = (const float*)d_in[17];
    const float* We2     = (const float*)d_in[18];
    const float* be2     = (const float*)d_in[19];
    const float* a2      = (const float*)d_in[20];
    const float* bo2     = (const float*)d_in[21];
    const float* Ws      = (const float*)d_in[22];
    const float* W_out   = (const float*)d_in[23];
    const float* b_out   = (const float*)d_in[24];
    float* out = (float*)d_out;

    cudaFuncSetAttribute(main_kernel, cudaFuncAttributeMaxDynamicSharedMemorySize, DYN_SMEM);

    setup_kernel<<<VDIM + 1, 128>>>(bl1, bo1, Wl2, bl2, Wr2, br2, be2, Ws);
    main_kernel<<<304, 256, DYN_SMEM>>>(E, E_idx, S, mask, chain_M, z,
                                        We2, a2, bl2, bo2, W_out, b_out, out);
}

// round 17
// speedup vs baseline: 1.1133x; 1.1133x over previous
#include <cuda_runtime.h>
#include <cuda_bf16.h>
#include <stdint.h>

#define N_NODES 4096
#define KNBR 32
#define CDIM 128
#define VDIM 21
#define NUM_TILES (N_NODES / 4)   // 4 nodes per tile, M = 128 rows
#define BWORDS 8192               // packed B fragments: 32 KB
#define DYN_SMEM (BWORDS * 4)
#define TPAD 132
#define GRID 296

__device__ float g_A[CDIM];
__device__ float g_const[CDIM];
__device__ float g_T[VDIM * CDIM];

__device__ __forceinline__ float lrelu(float x) { return x > 0.f ? x : 0.2f * x; }

__device__ __forceinline__ uint32_t cvt2(float2 v) {
    __nv_bfloat162 p = __floats2bfloat162_rn(v.x, v.y);
    return *(uint32_t*)&p;
}
__device__ __forceinline__ void mma16816(float* c, uint32_t a0, uint32_t a1,
                                         uint32_t a2, uint32_t a3,
                                         uint32_t b0, uint32_t b1) {
    asm volatile("mma.sync.aligned.m16n8k16.row.col.f32.bf16.bf16.f32 "
                 "{%0,%1,%2,%3}, {%4,%5,%6,%7}, {%8,%9}, {%0,%1,%2,%3};"
                 : "+f"(c[0]), "+f"(c[1]), "+f"(c[2]), "+f"(c[3])
                 : "r"(a0), "r"(a1), "r"(a2), "r"(a3), "r"(b0), "r"(b1));
}

// 22 blocks x 128 threads: block 0 -> g_A/g_const, blocks 1..21 -> g_T rows.
__global__ void setup_kernel(const float* __restrict__ bl1, const float* __restrict__ bo1,
                             const float* __restrict__ Wl2, const float* __restrict__ bl2,
                             const float* __restrict__ Wr2, const float* __restrict__ br2,
                             const float* __restrict__ be2, const float* __restrict__ Ws) {
    int c = threadIdx.x;
    int b = blockIdx.x;
    if (b == 0) {
        __shared__ float nv[CDIM];
        nv[c] = bl1[c] + bo1[c];
        __syncthreads();
        float a = 0.f, x = 0.f;
        #pragma unroll 8
        for (int j = 0; j < CDIM; j++) {
            a = fmaf(nv[j], Wl2[j * CDIM + c], a);
            x = fmaf(nv[j], Wr2[j * CDIM + c], x);
        }
        g_A[c] = a;
        g_const[c] = x + br2[c] + bl2[c] + be2[c];
    } else {
        int v = b - 1;
        float t = 0.f;
        #pragma unroll 8
        for (int h = 0; h < CDIM; h++)
            t = fmaf(Ws[v * CDIM + h], Wl2[(CDIM + h) * CDIM + c], t);
        g_T[v * CDIM + c] = t;
    }
}

__global__ void __launch_bounds__(256, 2)
main_kernel(const float* __restrict__ E, const int* __restrict__ E_idx,
            const int* __restrict__ S, const float* __restrict__ mask,
            const float* __restrict__ chain_M, const float* __restrict__ z,
            const float* __restrict__ We2, const float* __restrict__ a2,
            const float* __restrict__ bl2, const float* __restrict__ bo2,
            const float* __restrict__ W_out, const float* __restrict__ b_out,
            float* __restrict__ out) {
    extern __shared__ uint32_t Bsm[];       // packed We2^T fragments, uint4 granularity

    __shared__ __align__(16) float sT[VDIM * TPAD];
    __shared__ __align__(16) float sOut[4 * TPAD];
    __shared__ float sWo[CDIM * VDIM];      // W_out copy, [c][v]
    __shared__ float sbo[VDIM];
    __shared__ float sGA[CDIM];
    __shared__ float sGC[CDIM];
    __shared__ float sa2[CDIM];
    __shared__ float sB2[CDIM];             // bl2 + bo2
    // 4-deep buffers: tail(it) reads buf it&3 while run-ahead warps write (it+2)&3
    __shared__ float sWk[4][128];
    __shared__ int   sSk[4][128];
    __shared__ float sMask[4][4];
    __shared__ float sLogit[4][128];

    const int tid  = threadIdx.x;
    const int w    = tid >> 5;              // 0..7
    const int lane = tid & 31;
    const int gq   = lane >> 2;             // 0..7
    const int tq   = lane & 3;              // 0..3

    // ---- one-time init ----
    // Packed B as uint4: idx4 = (s*8+ntp)*32 + lane; comps = {nt=2ntp:(b0,b1), nt=2ntp+1:(b0,b1)}
    for (int i = tid; i < BWORDS; i += 256) {
        int comp = i & 3, l = (i >> 2) & 31, ntp = (i >> 7) & 7, s = (i >> 10) & 7;
        int gq2 = l >> 2, tq2 = l & 3;
        int nt = 2 * ntp + (comp >> 1);
        int b1 = comp & 1;
        int n  = nt * 8 + gq2;
        int j0 = (s * 8 + tq2 + 4 * b1) * 2;
        __nv_bfloat162 p = __floats2bfloat162_rn(We2[j0 * CDIM + n],
                                                 We2[(j0 + 1) * CDIM + n]);
        Bsm[i] = *(uint32_t*)&p;
    }
    for (int i = tid; i < VDIM * CDIM; i += 256) {
        sT[(i >> 7) * TPAD + (i & 127)] = g_T[i];
        sWo[i] = W_out[i];                  // same [c][v] layout
    }
    if (tid < CDIM) {
        sGA[tid] = g_A[tid];
        sGC[tid] = g_const[tid];
        sa2[tid] = a2[tid];
        sB2[tid] = bl2[tid] + bo2[tid];
    }
    if (tid < VDIM) sbo[tid] = b_out[tid];

    const int r0 = 16 * w + gq, r1 = r0 + 8;
    const int nd = w >> 1;
    const uint4* Bp4 = (const uint4*)Bsm + lane;

    // ---- prologue: metadata(tile0) into buf 0 + first A prefetch ----
    int tile = blockIdx.x;
    if (tid < 128) {
        int n = tile * 4 + (tid >> 5);
        int e = E_idx[n * KNBR + (tid & 31)];
        float kn = __fmul_rn(__fadd_rn(__fmul_rn(chain_M[n], mask[n]), 1e-4f), fabsf(z[n]));
        float ke = __fmul_rn(__fadd_rn(__fmul_rn(chain_M[e], mask[e]), 1e-4f), fabsf(z[e]));
        float attend = (kn > ke || (kn == ke && n > e)) ? 1.f : 0.f;
        sWk[0][tid] = attend * mask[n];
        sSk[0][tid] = S[e];
        if ((tid & 31) == 0) sMask[0][tid >> 5] = mask[n];
    }
    float2 st[8];
    {
        const float2* pb = (const float2*)E + ((size_t)tile * 128 + r0) * 64 + tq;
        #pragma unroll
        for (int s2 = 0; s2 < 2; s2++) {
            st[s2 * 4 + 0] = pb[8 * s2];
            st[s2 * 4 + 1] = pb[8 * s2 + 4];
            st[s2 * 4 + 2] = pb[8 * 64 + 8 * s2];
            st[s2 * 4 + 3] = pb[8 * 64 + 8 * s2 + 4];
        }
    }
    __syncthreads();

    for (int it = 0; tile < NUM_TILES; tile += GRID, it++) {
        const int p = it & 3;
        const float2* pb = (const float2*)E + ((size_t)tile * 128 + r0) * 64 + tq;

        // ---- GEMM (regs + constant Bsm only; no barrier needed) ----
        float acc[16][4];
        #pragma unroll
        for (int nt = 0; nt < 16; nt++)
            #pragma unroll
            for (int i = 0; i < 4; i++) acc[nt][i] = 0.f;

        #pragma unroll
        for (int q = 0; q < 4; q++) {
            uint32_t wf[8];
            #pragma unroll
            for (int u = 0; u < 8; u++) wf[u] = cvt2(st[u]);
            if (q < 3) {
                #pragma unroll
                for (int s2 = 0; s2 < 2; s2++) {
                    int s = (q + 1) * 2 + s2;
                    st[s2 * 4 + 0] = pb[8 * s];
                    st[s2 * 4 + 1] = pb[8 * s + 4];
                    st[s2 * 4 + 2] = pb[8 * 64 + 8 * s];
                    st[s2 * 4 + 3] = pb[8 * 64 + 8 * s + 4];
                }
            }
            #pragma unroll
            for (int s2 = 0; s2 < 2; s2++) {
                const int s = q * 2 + s2;
                const uint32_t a0 = wf[s2 * 4 + 0], a2r = wf[s2 * 4 + 1];
                const uint32_t a1 = wf[s2 * 4 + 2], a3  = wf[s2 * 4 + 3];
                #pragma unroll
                for (int ntp = 0; ntp < 8; ntp++) {
                    uint4 b = Bp4[(s * 8 + ntp) * 32];
                    mma16816(acc[2 * ntp],     a0, a1, a2r, a3, b.x, b.y);
                    mma16816(acc[2 * ntp + 1], a0, a1, a2r, a3, b.z, b.w);
                }
            }
        }

        // ---- epilogue: attention logits (consumes acc) ----
        {
            const float mn  = sMask[p][nd];
            const float wk0 = sWk[p][r0], wk1 = sWk[p][r1];
            const float* T0 = &sT[sSk[p][r0] * TPAD];
            const float* T1 = &sT[sSk[p][r1] * TPAD];
            float p0 = 0.f, p1 = 0.f;
            #pragma unroll
            for (int nt = 0; nt < 16; nt++) {
                #pragma unroll
                for (int i = 0; i < 2; i++) {
                    const int c = nt * 8 + tq * 2 + i;
                    const float ad = fmaf(sGA[c], mn, sGC[c]);
                    const float av = sa2[c];
                    p0 = fmaf(lrelu(acc[nt][i]     + ad + T0[c] * wk0), av, p0);
                    p1 = fmaf(lrelu(acc[nt][2 + i] + ad + T1[c] * wk1), av, p1);
                }
            }
            p0 += __shfl_xor_sync(0xffffffffu, p0, 1);
            p0 += __shfl_xor_sync(0xffffffffu, p0, 2);
            p1 += __shfl_xor_sync(0xffffffffu, p1, 1);
            p1 += __shfl_xor_sync(0xffffffffu, p1, 2);
            if (tq == 0) { sLogit[p][r0] = p0; sLogit[p][r1] = p1; }
        }

        // ---- prefetch next tile (A fragments + metadata -> buf (p+1)&3), pre-barrier ----
        {
            int ntile = tile + GRID;
            if (ntile >= NUM_TILES) ntile = NUM_TILES - 1;   // clamped dummy
            const int pn = (p + 1) & 3;
            const float2* nb = (const float2*)E + ((size_t)ntile * 128 + r0) * 64 + tq;
            #pragma unroll
            for (int s2 = 0; s2 < 2; s2++) {
                st[s2 * 4 + 0] = nb[8 * s2];
                st[s2 * 4 + 1] = nb[8 * s2 + 4];
                st[s2 * 4 + 2] = nb[8 * 64 + 8 * s2];
                st[s2 * 4 + 3] = nb[8 * 64 + 8 * s2 + 4];
            }
            if (tid < 128) {
                int n = ntile * 4 + (tid >> 5);
                int e = E_idx[n * KNBR + (tid & 31)];
                float kn = __fmul_rn(__fadd_rn(__fmul_rn(chain_M[n], mask[n]), 1e-4f), fabsf(z[n]));
                float ke = __fmul_rn(__fadd_rn(__fmul_rn(chain_M[e], mask[e]), 1e-4f), fabsf(z[e]));
                float attend = (kn > ke || (kn == ke && n > e)) ? 1.f : 0.f;
                sWk[pn][tid] = attend * mask[n];
                sSk[pn][tid] = S[e];
                if ((tid & 31) == 0) sMask[pn][tid >> 5] = mask[n];
            }
        }
        __syncthreads();   // the ONLY barrier per tile

        // ---- tail (warps 0-3, node = w); warps 4-7 run ahead into next GEMM ----
        if (w < 4) {
            float logit = sLogit[p][w * 32 + lane];
            float mx = logit;
            #pragma unroll
            for (int off = 16; off; off >>= 1)
                mx = fmaxf(mx, __shfl_xor_sync(0xffffffffu, mx, off));
            float e = expf(logit - mx);
            float ssum = e;
            #pragma unroll
            for (int off = 16; off; off >>= 1)
                ssum += __shfl_xor_sync(0xffffffffu, ssum, off);
            float aw = (e / ssum) * sWk[p][w * 32 + lane];
            int   sk = sSk[p][w * 32 + lane];

            const float mn = sMask[p][w];
            const int c0 = lane * 4;
            float o0 = fmaf(sGA[c0],     mn, sB2[c0]);
            float o1 = fmaf(sGA[c0 + 1], mn, sB2[c0 + 1]);
            float o2 = fmaf(sGA[c0 + 2], mn, sB2[c0 + 2]);
            float o3 = fmaf(sGA[c0 + 3], mn, sB2[c0 + 3]);
            #pragma unroll
            for (int k = 0; k < KNBR; k++) {
                float awk = __shfl_sync(0xffffffffu, aw, k);
                int   skk = __shfl_sync(0xffffffffu, sk, k);
                const float4 t = *(const float4*)&sT[skk * TPAD + c0];
                o0 = fmaf(awk, t.x, o0);
                o1 = fmaf(awk, t.y, o1);
                o2 = fmaf(awk, t.z, o2);
                o3 = fmaf(awk, t.w, o3);
            }
            *(float4*)&sOut[w * TPAD + c0] = make_float4(o0, o1, o2, o3);
            __syncwarp();

            // V=21 projection from smem, 4 independent partials
            float L = -1e30f;
            if (lane < VDIM) {
                const float* sO = &sOut[w * TPAD];
                float L0 = 0.f, L1 = 0.f, L2 = 0.f, L3 = 0.f;
                #pragma unroll 8
                for (int c = 0; c < CDIM; c += 4) {
                    L0 = fmaf(sO[c],     sWo[c * VDIM + lane],       L0);
                    L1 = fmaf(sO[c + 1], sWo[(c + 1) * VDIM + lane], L1);
                    L2 = fmaf(sO[c + 2], sWo[(c + 2) * VDIM + lane], L2);
                    L3 = fmaf(sO[c + 3], sWo[(c + 3) * VDIM + lane], L3);
                }
                L = sbo[lane] + (L0 + L1) + (L2 + L3);
            }
            float mx2 = L;
            #pragma unroll
            for (int off = 16; off; off >>= 1)
                mx2 = fmaxf(mx2, __shfl_xor_sync(0xffffffffu, mx2, off));
            float e2 = (lane < VDIM) ? expf(L - mx2) : 0.f;
            float s2 = e2;
            #pragma unroll
            for (int off = 16; off; off >>= 1)
                s2 += __shfl_xor_sync(0xffffffffu, s2, off);
            if (lane < VDIM)
                out[(tile * 4 + w) * VDIM + lane] = L - mx2 - logf(s2);
        }
        // no trailing barrier: 4-deep buffers make the one-iteration run-ahead race-free
    }
}

extern "C" void kernel_launch(void* const* d_in, const int* in_sizes, int n_in,
                              void* d_out, int out_size) {
    const float* E       = (const float*)d_in[0];
    const int*   E_idx   = (const int*)  d_in[1];
    const int*   S       = (const int*)  d_in[2];
    const float* mask    = (const float*)d_in[3];
    const float* chain_M = (const float*)d_in[4];
    const float* z       = (const float*)d_in[5];
    const float* bl1     = (const float*)d_in[7];
    const float* bo1     = (const float*)d_in[13];
    const float* Wl2     = (const float*)d_in[14];
    const float* bl2     = (const float*)d_in[15];
    const float* Wr2     = (const float*)d_in[16];
    const float* br2     = (const float*)d_in[17];
    const float* We2     = (const float*)d_in[18];
    const float* be2     = (const float*)d_in[19];
    const float* a2      = (const float*)d_in[20];
    const float* bo2     = (const float*)d_in[21];
    const float* Ws      = (const float*)d_in[22];
    const float* W_out   = (const float*)d_in[23];
    const float* b_out   = (const float*)d_in[24];
    float* out = (float*)d_out;

    cudaFuncSetAttribute(main_kernel, cudaFuncAttributeMaxDynamicSharedMemorySize, DYN_SMEM);

    setup_kernel<<<VDIM + 1, 128>>>(bl1, bo1, Wl2, bl2, Wr2, br2, be2, Ws);
    main_kernel<<<GRID, 256, DYN_SMEM>>>(E, E_idx, S, mask, chain_M, z,
                                         We2, a2, bl2, bo2, W_out, b_out, out);
}